// round 4
// baseline (speedup 1.0000x reference)
#include <cuda_runtime.h>
#include <cstdint>

// ---------------- problem constants ----------------
#define N_B    32
#define C_IN   256
#define L_LEN  4096
#define C_OUT  256
#define KW     9
#define GROUPS 4
#define CPG    64
#define OPG    64
#define C_DIM  128
#define PAD    4

#define L_TILE 256
#define NTHR   128                          // 4 warps; warp tile = 64 l x 64 oc
#define XS_STRIDE 268                       // words; %32==12, 16B-aligned rows

// smem layout (bytes)
#define SM_XS    0                          // 64 x 268 u32 = 68,608 (also epilogue buf)
#define SM_B0    (64 * XS_STRIDE * 4)       // 16 KB fragment-ordered B tile
#define SM_B1    (SM_B0 + 16384)
#define SM_TOTAL (SM_B1 + 16384)            // 101,376 B  (x2 CTA/SM = 202,752)

// ---------------- device scratch ----------------
__device__ float g_ctx[N_B * C_OUT];
__device__ unsigned int g_wt[GROUPS * KW * 4096];   // fragment-ordered tf32 B tiles

__device__ __forceinline__ uint32_t tf32rn(float f) {
    uint32_t r;
    asm("cvt.rna.tf32.f32 %0, %1;" : "=r"(r) : "f"(f));
    return r;
}
__device__ __forceinline__ uint32_t smem_u32(const void* p) {
    uint32_t a;
    asm("{ .reg .u64 t; cvta.to.shared.u64 t, %1; cvt.u32.u64 %0, t; }" : "=r"(a) : "l"(p));
    return a;
}
__device__ __forceinline__ void cp16(uint32_t dst, const void* src) {
    asm volatile("cp.async.cg.shared.global [%0], [%1], 16;" :: "r"(dst), "l"(src));
}
#define CP_COMMIT() asm volatile("cp.async.commit_group;" ::: "memory")
#define CP_WAIT0()  asm volatile("cp.async.wait_group 0;" ::: "memory")

__device__ __forceinline__ void mma_tf32(float* d, const uint32_t* a, uint32_t b0, uint32_t b1) {
    asm volatile(
        "mma.sync.aligned.m16n8k8.row.col.f32.tf32.tf32.f32 "
        "{%0,%1,%2,%3}, {%4,%5,%6,%7}, {%8,%9}, {%0,%1,%2,%3};"
        : "+f"(d[0]), "+f"(d[1]), "+f"(d[2]), "+f"(d[3])
        : "r"(a[0]), "r"(a[1]), "r"(a[2]), "r"(a[3]), "r"(b0), "r"(b1));
}

// ---------------------------------------------------------------------------
// prep_kernel: blocks [0,36) -> weight fragment tiles; [36,164) -> ctx GEMM.
// wt order per (g,k): idx = ((s*4+q)*32+lane)*4 + r
//   f = 2q + (r>>1); oc = 8f + (lane>>2); ic = 8s + (lane&3) + 4*(r&1)
// ---------------------------------------------------------------------------
__global__ void prep_kernel(const float* __restrict__ w,
                            const float* __restrict__ c,
                            const float* __restrict__ cw) {
    int bx = blockIdx.x, tid = threadIdx.x;
    if (bx < GROUPS * KW) {
        int g = bx / KW, k = bx - g * KW;
        unsigned int* dst = g_wt + (size_t)bx * 4096;
        for (int idx = tid; idx < 4096; idx += 256) {
            int r    = idx & 3;
            int lane = (idx >> 2) & 31;
            int q    = (idx >> 7) & 3;
            int s    = idx >> 9;
            int f    = 2 * q + (r >> 1);
            int oc   = 8 * f + (lane >> 2);
            int ic   = 8 * s + (lane & 3) + 4 * (r & 1);
            dst[idx] = tf32rn(w[(size_t)(g * OPG + oc) * (CPG * KW) + ic * KW + k]);
        }
    } else {
        // ctx: 4 threads per output, 64 outputs per block
        int o  = (bx - GROUPS * KW) * 64 + (tid >> 2);   // 0..8191
        int n  = o >> 8, oc = o & 255;
        const float* cr = c  + (size_t)n  * C_DIM + (tid & 3) * 32;
        const float* wr = cw + (size_t)oc * C_DIM + (tid & 3) * 32;
        float s = 0.f;
#pragma unroll 8
        for (int d = 0; d < 32; d++) s += cr[d] * wr[d];
        s += __shfl_down_sync(0xFFFFFFFFu, s, 2);
        s += __shfl_down_sync(0xFFFFFFFFu, s, 1);
        if ((tid & 3) == 0) g_ctx[o] = s;
    }
}

// ---------------------------------------------------------------------------
// conv_kernel: grouped conv as implicit GEMM on mma.sync (tf32, fp32 accum).
// Block (lt, g, n): 256 l x 64 oc, 4 warps; warp = 64 l x 64 oc.
// ---------------------------------------------------------------------------
__global__ void __launch_bounds__(NTHR, 2)
conv_kernel(const float* __restrict__ x, const float* __restrict__ bias,
            float* __restrict__ out) {
    extern __shared__ char smem[];
    uint32_t* xs = (uint32_t*)(smem + SM_XS);
    const uint32_t sb = smem_u32(smem);

    const int tid = threadIdx.x;
    const int wid = tid >> 5, lane = tid & 31;
    const int lt = blockIdx.x, g = blockIdx.y, n = blockIdx.z;
    const int l0 = lt * L_TILE;

    // ---- prologue: async-load B_0, stage x tile (tf32-rounded) ----
    {
        const char* src = (const char*)(g_wt + (size_t)(g * KW) * 4096) + tid * 16;
        uint32_t dst = sb + SM_B0 + tid * 16;
#pragma unroll
        for (int i = 0; i < 8; i++) cp16(dst + i * NTHR * 16, src + i * NTHR * 16);
        CP_COMMIT();
    }
    {
        const float* xb = x + ((size_t)(n * C_IN + g * CPG)) * L_LEN;
        for (int idx = tid; idx < CPG * (L_TILE + 8); idx += NTHR) {
            int ic = idx / (L_TILE + 8);
            int j  = idx - ic * (L_TILE + 8);
            int gl = l0 - PAD + j;
            float v = (gl >= 0 && gl < L_LEN) ? xb[(size_t)ic * L_LEN + gl] : 0.f;
            xs[ic * XS_STRIDE + j] = tf32rn(v);
        }
    }
    CP_WAIT0();
    __syncthreads();

    // ---- accumulators: warp tile 64 l x 64 oc = 4 (mi) x 8 (f) frags ----
    float d[4][8][4];
#pragma unroll
    for (int mi = 0; mi < 4; mi++)
#pragma unroll
        for (int f = 0; f < 8; f++)
#pragma unroll
            for (int r = 0; r < 4; r++) d[mi][f][r] = 0.f;

    const int ml = wid * 64;
    const int ar = lane >> 2;      // a-frag row
    const int ac = lane & 3;       // a-frag col (ic offset)

#pragma unroll 1
    for (int k = 0; k < KW; k++) {
        const uint32_t* bb = (const uint32_t*)(smem + ((k & 1) ? SM_B1 : SM_B0));

        // async-prefetch next tap's B into the other buffer
        if (k < KW - 1) {
            const char* src = (const char*)(g_wt + (size_t)(g * KW + k + 1) * 4096) + tid * 16;
            uint32_t dst = sb + ((k & 1) ? SM_B0 : SM_B1) + tid * 16;
#pragma unroll
            for (int i = 0; i < 8; i++) cp16(dst + i * NTHR * 16, src + i * NTHR * 16);
            CP_COMMIT();
        }

#pragma unroll
        for (int s = 0; s < 8; s++) {
            // A fragments from shifted x window (conflict-free: banks 12*ac+ar)
            uint32_t a[4][4];
            {
                const uint32_t* r0 = xs + (s * 8 + ac) * XS_STRIDE + (ml + ar + k);
                const uint32_t* r4 = r0 + 4 * XS_STRIDE;
#pragma unroll
                for (int mi = 0; mi < 4; mi++) {
                    a[mi][0] = r0[mi * 16];
                    a[mi][1] = r0[mi * 16 + 8];
                    a[mi][2] = r4[mi * 16];
                    a[mi][3] = r4[mi * 16 + 8];
                }
            }
            // B fragments: 4 conflict-free lds.128
            uint4 bq[4];
            {
                const uint4* bsrc = (const uint4*)bb + s * 4 * 32 + lane;
#pragma unroll
                for (int q = 0; q < 4; q++) bq[q] = bsrc[q * 32];
            }
#pragma unroll
            for (int mi = 0; mi < 4; mi++) {
#pragma unroll
                for (int q = 0; q < 4; q++) {
                    mma_tf32(d[mi][2 * q],     a[mi], bq[q].x, bq[q].y);
                    mma_tf32(d[mi][2 * q + 1], a[mi], bq[q].z, bq[q].w);
                }
            }
        }

        if (k < KW - 1) CP_WAIT0();
        __syncthreads();
    }

    // ---- epilogue: stage through smem (alias xs), coalesced float4 out ----
    float* ep = (float*)(smem + SM_XS);   // [oc][l], stride XS_STRIDE
#pragma unroll
    for (int mi = 0; mi < 4; mi++) {
#pragma unroll
        for (int f = 0; f < 8; f++) {
            int l  = ml + 16 * mi + ar;
            int oc = 8 * f + 2 * ac;
            ep[oc * XS_STRIDE + l]           = d[mi][f][0];
            ep[(oc + 1) * XS_STRIDE + l]     = d[mi][f][1];
            ep[oc * XS_STRIDE + l + 8]       = d[mi][f][2];
            ep[(oc + 1) * XS_STRIDE + l + 8] = d[mi][f][3];
        }
    }
    __syncthreads();

#pragma unroll
    for (int i = 0; i < 16; i++) {
        int oc  = wid * 16 + i;
        int goc = g * OPG + oc;
        float add = g_ctx[n * C_OUT + goc] + bias[goc];
        const float4* src = (const float4*)(ep + oc * XS_STRIDE);
        float4* dst = (float4*)(out + ((size_t)(n * C_OUT + goc)) * L_LEN + l0);
#pragma unroll
        for (int it = 0; it < 2; it++) {
            float4 v = src[lane + it * 32];
            v.x += add; v.y += add; v.z += add; v.w += add;
            dst[lane + it * 32] = v;
        }
    }
}

// ---------------------------------------------------------------------------
extern "C" void kernel_launch(void* const* d_in, const int* in_sizes, int n_in,
                              void* d_out, int out_size) {
    const float* x    = (const float*)d_in[0];  // (32, 256, 4096)
    const float* c    = (const float*)d_in[1];  // (32, 128)
    const float* w    = (const float*)d_in[2];  // (256, 64, 9)
    const float* cw   = (const float*)d_in[3];  // (256, 128)
    const float* bias = (const float*)d_in[4];  // (256,)
    float* out = (float*)d_out;                 // (32, 256, 4096)

    cudaFuncSetAttribute(conv_kernel, cudaFuncAttributeMaxDynamicSharedMemorySize, SM_TOTAL);

    prep_kernel<<<GROUPS * KW + 128, 256>>>(w, c, cw);
    dim3 grid(L_LEN / L_TILE, GROUPS, N_B);     // (16, 4, 32)
    conv_kernel<<<grid, NTHR, SM_TOTAL>>>(x, bias, out);
}

// round 5
// speedup vs baseline: 1.1698x; 1.1698x over previous
#include <cuda_runtime.h>
#include <cstdint>

// ---------------- problem constants ----------------
#define N_B    32
#define C_IN   256
#define L_LEN  4096
#define C_OUT  256
#define KW     9
#define GROUPS 4
#define CPG    64
#define OPG    64
#define C_DIM  128
#define PAD    4

#define L_TILE 256
#define NTHR   256                          // 8 warps; warp tile = 32 l x 64 oc
#define XS_STRIDE 268                       // words; %32==12, 16B-aligned rows

// smem layout (bytes)
#define SM_XS    0                          // 64 x 268 u32 = 68,608 (also epilogue buf)
#define SM_B0    (64 * XS_STRIDE * 4)       // 16 KB fragment-ordered B tile
#define SM_B1    (SM_B0 + 16384)
#define SM_TOTAL (SM_B1 + 16384)            // 101,376 B (x2 CTA/SM = 202,752)

// ---------------- device scratch ----------------
__device__ float g_ctx[N_B * C_OUT];
__device__ unsigned int g_wt[GROUPS * KW * 4096];   // fragment-ordered tf32 B tiles

__device__ __forceinline__ uint32_t tf32rn(float f) {
    uint32_t r;
    asm("cvt.rna.tf32.f32 %0, %1;" : "=r"(r) : "f"(f));
    return r;
}
__device__ __forceinline__ uint32_t smem_u32(const void* p) {
    uint32_t a;
    asm("{ .reg .u64 t; cvta.to.shared.u64 t, %1; cvt.u32.u64 %0, t; }" : "=r"(a) : "l"(p));
    return a;
}
__device__ __forceinline__ void cp16(uint32_t dst, const void* src) {
    asm volatile("cp.async.cg.shared.global [%0], [%1], 16;" :: "r"(dst), "l"(src));
}
#define CP_COMMIT() asm volatile("cp.async.commit_group;" ::: "memory")
#define CP_WAIT0()  asm volatile("cp.async.wait_group 0;" ::: "memory")

__device__ __forceinline__ void mma_tf32(float* d, const uint32_t* a, uint32_t b0, uint32_t b1) {
    asm volatile(
        "mma.sync.aligned.m16n8k8.row.col.f32.tf32.tf32.f32 "
        "{%0,%1,%2,%3}, {%4,%5,%6,%7}, {%8,%9}, {%0,%1,%2,%3};"
        : "+f"(d[0]), "+f"(d[1]), "+f"(d[2]), "+f"(d[3])
        : "r"(a[0]), "r"(a[1]), "r"(a[2]), "r"(a[3]), "r"(b0), "r"(b1));
}

// ---------------------------------------------------------------------------
// prep_kernel: blocks [0,36) -> weight fragment tiles; [36,164) -> ctx GEMM.
// ---------------------------------------------------------------------------
__global__ void prep_kernel(const float* __restrict__ w,
                            const float* __restrict__ c,
                            const float* __restrict__ cw) {
    int bx = blockIdx.x, tid = threadIdx.x;
    if (bx < GROUPS * KW) {
        int g = bx / KW, k = bx - g * KW;
        unsigned int* dst = g_wt + (size_t)bx * 4096;
        for (int idx = tid; idx < 4096; idx += 256) {
            int r    = idx & 3;
            int lane = (idx >> 2) & 31;
            int q    = (idx >> 7) & 3;
            int s    = idx >> 9;
            int f    = 2 * q + (r >> 1);
            int oc   = 8 * f + (lane >> 2);
            int ic   = 8 * s + (lane & 3) + 4 * (r & 1);
            dst[idx] = tf32rn(w[(size_t)(g * OPG + oc) * (CPG * KW) + ic * KW + k]);
        }
    } else {
        int o  = (bx - GROUPS * KW) * 64 + (tid >> 2);   // 0..8191
        int n  = o >> 8, oc = o & 255;
        const float* cr = c  + (size_t)n  * C_DIM + (tid & 3) * 32;
        const float* wr = cw + (size_t)oc * C_DIM + (tid & 3) * 32;
        float s = 0.f;
#pragma unroll 8
        for (int d = 0; d < 32; d++) s += cr[d] * wr[d];
        s += __shfl_down_sync(0xFFFFFFFFu, s, 2);
        s += __shfl_down_sync(0xFFFFFFFFu, s, 1);
        if ((tid & 3) == 0) g_ctx[o] = s;
    }
}

// ---------------------------------------------------------------------------
// conv_kernel: grouped conv as implicit GEMM (tf32 mma.sync, fp32 accum).
// Block (lt, g, n): 256 l x 64 oc, 8 warps; warp = 32 l x 64 oc.
// Software-pipelined inner loop; cp.async double-buffered B across taps.
// ---------------------------------------------------------------------------
__global__ void __launch_bounds__(NTHR, 2)
conv_kernel(const float* __restrict__ x, const float* __restrict__ bias,
            float* __restrict__ out) {
    extern __shared__ char smem[];
    uint32_t* xs = (uint32_t*)(smem + SM_XS);
    const uint32_t sb = smem_u32(smem);

    const int tid = threadIdx.x;
    const int wid = tid >> 5, lane = tid & 31;
    const int lt = blockIdx.x, g = blockIdx.y, n = blockIdx.z;
    const int l0 = lt * L_TILE;

    // ---- prologue: async-load B_0; stage x tile (tf32-rounded) ----
    {
        const char* src = (const char*)(g_wt + (size_t)(g * KW) * 4096) + tid * 16;
        uint32_t dst = sb + SM_B0 + tid * 16;
#pragma unroll
        for (int i = 0; i < 4; i++) cp16(dst + i * NTHR * 16, src + i * NTHR * 16);
        CP_COMMIT();
    }
    {
        const float* xb = x + ((size_t)(n * C_IN + g * CPG)) * L_LEN;
        for (int idx = tid; idx < CPG * (L_TILE + 8); idx += NTHR) {
            int ic = idx / (L_TILE + 8);
            int j  = idx - ic * (L_TILE + 8);
            int gl = l0 - PAD + j;
            float v = (gl >= 0 && gl < L_LEN) ? xb[(size_t)ic * L_LEN + gl] : 0.f;
            xs[ic * XS_STRIDE + j] = tf32rn(v);
        }
    }
    CP_WAIT0();
    __syncthreads();

    // ---- accumulators: warp tile 32 l x 64 oc = 2 (mi) x 8 (f) frags ----
    float d[2][8][4];
#pragma unroll
    for (int mi = 0; mi < 2; mi++)
#pragma unroll
        for (int f = 0; f < 8; f++)
#pragma unroll
            for (int r = 0; r < 4; r++) d[mi][f][r] = 0.f;

    const int ml = wid * 32;
    const int ar = lane >> 2;      // a-frag row
    const int ac = lane & 3;       // a-frag col (ic offset)

#pragma unroll 1
    for (int k = 0; k < KW; k++) {
        const uint32_t* bb = (const uint32_t*)(smem + ((k & 1) ? SM_B1 : SM_B0));

        // async-prefetch next tap's B into the other buffer
        if (k < KW - 1) {
            const char* src = (const char*)(g_wt + (size_t)(g * KW + k + 1) * 4096) + tid * 16;
            uint32_t dst = sb + ((k & 1) ? SM_B0 : SM_B1) + tid * 16;
#pragma unroll
            for (int i = 0; i < 4; i++) cp16(dst + i * NTHR * 16, src + i * NTHR * 16);
            CP_COMMIT();
        }

        // -- software-pipelined s-loop: load frags for s+1 during MMAs of s --
        uint32_t a_cur[2][4], a_nxt[2][4];
        uint4    b_cur[4],    b_nxt[4];
        {
            const uint32_t* r0 = xs + ac * XS_STRIDE + (ml + ar + k);
            const uint32_t* r4 = r0 + 4 * XS_STRIDE;
#pragma unroll
            for (int mi = 0; mi < 2; mi++) {
                a_cur[mi][0] = r0[mi * 16];
                a_cur[mi][1] = r0[mi * 16 + 8];
                a_cur[mi][2] = r4[mi * 16];
                a_cur[mi][3] = r4[mi * 16 + 8];
            }
            const uint4* bsrc = (const uint4*)bb + lane;
#pragma unroll
            for (int q = 0; q < 4; q++) b_cur[q] = bsrc[q * 32];
        }

#pragma unroll
        for (int s = 0; s < 8; s++) {
            if (s < 7) {
                const uint32_t* r0 = xs + ((s + 1) * 8 + ac) * XS_STRIDE + (ml + ar + k);
                const uint32_t* r4 = r0 + 4 * XS_STRIDE;
#pragma unroll
                for (int mi = 0; mi < 2; mi++) {
                    a_nxt[mi][0] = r0[mi * 16];
                    a_nxt[mi][1] = r0[mi * 16 + 8];
                    a_nxt[mi][2] = r4[mi * 16];
                    a_nxt[mi][3] = r4[mi * 16 + 8];
                }
                const uint4* bsrc = (const uint4*)bb + (s + 1) * 128 + lane;
#pragma unroll
                for (int q = 0; q < 4; q++) b_nxt[q] = bsrc[q * 32];
            }
#pragma unroll
            for (int mi = 0; mi < 2; mi++) {
#pragma unroll
                for (int q = 0; q < 4; q++) {
                    mma_tf32(d[mi][2 * q],     a_cur[mi], b_cur[q].x, b_cur[q].y);
                    mma_tf32(d[mi][2 * q + 1], a_cur[mi], b_cur[q].z, b_cur[q].w);
                }
            }
#pragma unroll
            for (int mi = 0; mi < 2; mi++)
#pragma unroll
                for (int r = 0; r < 4; r++) a_cur[mi][r] = a_nxt[mi][r];
#pragma unroll
            for (int q = 0; q < 4; q++) b_cur[q] = b_nxt[q];
        }

        if (k < KW - 1) CP_WAIT0();
        __syncthreads();
    }

    // ---- epilogue: stage through smem (alias xs), coalesced float4 out ----
    float* ep = (float*)(smem + SM_XS);   // [oc][l], stride XS_STRIDE
#pragma unroll
    for (int mi = 0; mi < 2; mi++) {
#pragma unroll
        for (int f = 0; f < 8; f++) {
            int l  = ml + 16 * mi + ar;
            int oc = 8 * f + 2 * ac;
            ep[oc * XS_STRIDE + l]           = d[mi][f][0];
            ep[(oc + 1) * XS_STRIDE + l]     = d[mi][f][1];
            ep[oc * XS_STRIDE + l + 8]       = d[mi][f][2];
            ep[(oc + 1) * XS_STRIDE + l + 8] = d[mi][f][3];
        }
    }
    __syncthreads();

#pragma unroll
    for (int i = 0; i < 8; i++) {
        int oc  = wid * 8 + i;
        int goc = g * OPG + oc;
        float add = g_ctx[n * C_OUT + goc] + bias[goc];
        const float4* src = (const float4*)(ep + oc * XS_STRIDE);
        float4* dst = (float4*)(out + ((size_t)(n * C_OUT + goc)) * L_LEN + l0);
#pragma unroll
        for (int it = 0; it < 2; it++) {
            float4 v = src[lane + it * 32];
            v.x += add; v.y += add; v.z += add; v.w += add;
            dst[lane + it * 32] = v;
        }
    }
}

// ---------------------------------------------------------------------------
extern "C" void kernel_launch(void* const* d_in, const int* in_sizes, int n_in,
                              void* d_out, int out_size) {
    const float* x    = (const float*)d_in[0];  // (32, 256, 4096)
    const float* c    = (const float*)d_in[1];  // (32, 128)
    const float* w    = (const float*)d_in[2];  // (256, 64, 9)
    const float* cw   = (const float*)d_in[3];  // (256, 128)
    const float* bias = (const float*)d_in[4];  // (256,)
    float* out = (float*)d_out;                 // (32, 256, 4096)

    cudaFuncSetAttribute(conv_kernel, cudaFuncAttributeMaxDynamicSharedMemorySize, SM_TOTAL);

    prep_kernel<<<GROUPS * KW + 128, 256>>>(w, c, cw);
    dim3 grid(L_LEN / L_TILE, GROUPS, N_B);     // (16, 4, 32)
    conv_kernel<<<grid, NTHR, SM_TOTAL>>>(x, bias, out);
}

// round 6
// speedup vs baseline: 1.3250x; 1.1327x over previous
#include <cuda_runtime.h>
#include <cstdint>

// ---------------- problem constants ----------------
#define N_B    32
#define C_IN   256
#define L_LEN  4096
#define C_OUT  256
#define KW     9
#define GROUPS 4
#define CPG    64
#define OPG    64
#define C_DIM  128
#define PAD    4

#define L_TILE 256
#define NTHR   256                          // 8 warps; warp tile = 32 l x 64 oc
#define XS_STRIDE 264                       // words; %32==8 -> A-frag LDS conflict-free
#define EP_STRIDE 260                       // words; %16==4 -> epilogue STS conflict-free

// smem layout (bytes)
#define SM_XS    0                          // 64 x 264 u32 = 67,584 (also epilogue buf)
#define SM_B0    (64 * XS_STRIDE * 4)       // 16 KB fragment-ordered B tile
#define SM_B1    (SM_B0 + 16384)
#define SM_TOTAL (SM_B1 + 16384)            // 100,352 B (x2 CTA/SM = 200,704)

// ---------------- device scratch ----------------
__device__ float g_ctx[N_B * C_OUT];
__device__ unsigned int g_wt[GROUPS * KW * 4096];   // fragment-ordered tf32 B tiles

__device__ __forceinline__ uint32_t tf32rn(float f) {
    uint32_t r;
    asm("cvt.rna.tf32.f32 %0, %1;" : "=r"(r) : "f"(f));
    return r;
}
__device__ __forceinline__ uint32_t smem_u32(const void* p) {
    uint32_t a;
    asm("{ .reg .u64 t; cvta.to.shared.u64 t, %1; cvt.u32.u64 %0, t; }" : "=r"(a) : "l"(p));
    return a;
}
__device__ __forceinline__ void cp16(uint32_t dst, const void* src) {
    asm volatile("cp.async.cg.shared.global [%0], [%1], 16;" :: "r"(dst), "l"(src));
}
#define CP_COMMIT() asm volatile("cp.async.commit_group;" ::: "memory")
#define CP_WAIT0()  asm volatile("cp.async.wait_group 0;" ::: "memory")

// non-volatile: pure register semantics, let ptxas schedule freely
__device__ __forceinline__ void mma_tf32(float* d, const uint32_t* a, uint32_t b0, uint32_t b1) {
    asm("mma.sync.aligned.m16n8k8.row.col.f32.tf32.tf32.f32 "
        "{%0,%1,%2,%3}, {%4,%5,%6,%7}, {%8,%9}, {%0,%1,%2,%3};"
        : "+f"(d[0]), "+f"(d[1]), "+f"(d[2]), "+f"(d[3])
        : "r"(a[0]), "r"(a[1]), "r"(a[2]), "r"(a[3]), "r"(b0), "r"(b1));
}

// ---------------------------------------------------------------------------
// prep_kernel: blocks [0,36) -> weight fragment tiles; [36,164) -> ctx GEMM.
// ---------------------------------------------------------------------------
__global__ void prep_kernel(const float* __restrict__ w,
                            const float* __restrict__ c,
                            const float* __restrict__ cw) {
    int bx = blockIdx.x, tid = threadIdx.x;
    if (bx < GROUPS * KW) {
        int g = bx / KW, k = bx - g * KW;
        unsigned int* dst = g_wt + (size_t)bx * 4096;
        for (int idx = tid; idx < 4096; idx += 256) {
            int r    = idx & 3;
            int lane = (idx >> 2) & 31;
            int q    = (idx >> 7) & 3;
            int s    = idx >> 9;
            int f    = 2 * q + (r >> 1);
            int oc   = 8 * f + (lane >> 2);
            int ic   = 8 * s + (lane & 3) + 4 * (r & 1);
            dst[idx] = tf32rn(w[(size_t)(g * OPG + oc) * (CPG * KW) + ic * KW + k]);
        }
    } else {
        int o  = (bx - GROUPS * KW) * 64 + (tid >> 2);   // 0..8191
        int n  = o >> 8, oc = o & 255;
        const float* cr = c  + (size_t)n  * C_DIM + (tid & 3) * 32;
        const float* wr = cw + (size_t)oc * C_DIM + (tid & 3) * 32;
        float s = 0.f;
#pragma unroll 8
        for (int d = 0; d < 32; d++) s += cr[d] * wr[d];
        s += __shfl_down_sync(0xFFFFFFFFu, s, 2);
        s += __shfl_down_sync(0xFFFFFFFFu, s, 1);
        if ((tid & 3) == 0) g_ctx[o] = s;
    }
}

// ---------------------------------------------------------------------------
// conv_kernel: grouped conv as implicit GEMM (tf32 mma.sync, fp32 accum).
// Block (lt, g, n): 256 l x 64 oc, 8 warps; warp = 32 l x 64 oc.
// ---------------------------------------------------------------------------
__global__ void __launch_bounds__(NTHR, 2)
conv_kernel(const float* __restrict__ x, const float* __restrict__ bias,
            float* __restrict__ out) {
    extern __shared__ char smem[];
    uint32_t* xs = (uint32_t*)(smem + SM_XS);
    const uint32_t sb = smem_u32(smem);

    const int tid = threadIdx.x;
    const int wid = tid >> 5, lane = tid & 31;
    const int lt = blockIdx.x, g = blockIdx.y, n = blockIdx.z;
    const int l0 = lt * L_TILE;

    // ---- prologue: async-load B_0; stage x tile (tf32-rounded) ----
    {
        const char* src = (const char*)(g_wt + (size_t)(g * KW) * 4096) + tid * 16;
        uint32_t dst = sb + SM_B0 + tid * 16;
#pragma unroll
        for (int i = 0; i < 4; i++) cp16(dst + i * NTHR * 16, src + i * NTHR * 16);
        CP_COMMIT();
    }
    {
        const float* xb = x + ((size_t)(n * C_IN + g * CPG)) * L_LEN;
        for (int idx = tid; idx < CPG * (L_TILE + 8); idx += NTHR) {
            int ic = idx / (L_TILE + 8);
            int j  = idx - ic * (L_TILE + 8);
            int gl = l0 - PAD + j;
            float v = (gl >= 0 && gl < L_LEN) ? xb[(size_t)ic * L_LEN + gl] : 0.f;
            xs[ic * XS_STRIDE + j] = tf32rn(v);
        }
    }
    CP_WAIT0();
    __syncthreads();

    // ---- accumulators: warp tile 32 l x 64 oc = 2 (mi) x 8 (f) frags ----
    float d[2][8][4];
#pragma unroll
    for (int mi = 0; mi < 2; mi++)
#pragma unroll
        for (int f = 0; f < 8; f++)
#pragma unroll
            for (int r = 0; r < 4; r++) d[mi][f][r] = 0.f;

    const int ml = wid * 32;
    const int ar = lane >> 2;      // a-frag row
    const int ac = lane & 3;       // a-frag col (ic offset)

#pragma unroll 1
    for (int k = 0; k < KW; k++) {
        const uint32_t* bb = (const uint32_t*)(smem + ((k & 1) ? SM_B1 : SM_B0));

        // async-prefetch next tap's B into the other buffer
        if (k < KW - 1) {
            const char* src = (const char*)(g_wt + (size_t)(g * KW + k + 1) * 4096) + tid * 16;
            uint32_t dst = sb + ((k & 1) ? SM_B0 : SM_B1) + tid * 16;
#pragma unroll
            for (int i = 0; i < 4; i++) cp16(dst + i * NTHR * 16, src + i * NTHR * 16);
            CP_COMMIT();
        }

#pragma unroll
        for (int s = 0; s < 8; s++) {
            // A fragments (stride%32==8 -> banks 8*ac+ar: conflict-free)
            uint32_t a[2][4];
            {
                const uint32_t* r0 = xs + (s * 8 + ac) * XS_STRIDE + (ml + ar + k);
                const uint32_t* r4 = r0 + 4 * XS_STRIDE;
#pragma unroll
                for (int mi = 0; mi < 2; mi++) {
                    a[mi][0] = r0[mi * 16];
                    a[mi][1] = r0[mi * 16 + 8];
                    a[mi][2] = r4[mi * 16];
                    a[mi][3] = r4[mi * 16 + 8];
                }
            }
            // B fragments: 4 conflict-free lds.128
            uint4 bq[4];
            {
                const uint4* bsrc = (const uint4*)bb + s * 4 * 32 + lane;
#pragma unroll
                for (int q = 0; q < 4; q++) bq[q] = bsrc[q * 32];
            }
#pragma unroll
            for (int mi = 0; mi < 2; mi++) {
#pragma unroll
                for (int q = 0; q < 4; q++) {
                    mma_tf32(d[mi][2 * q],     a[mi], bq[q].x, bq[q].y);
                    mma_tf32(d[mi][2 * q + 1], a[mi], bq[q].z, bq[q].w);
                }
            }
        }

        if (k < KW - 1) CP_WAIT0();
        __syncthreads();
    }

    // ---- epilogue: stage through smem (alias xs), coalesced float4 out ----
    float* ep = (float*)(smem + SM_XS);   // [oc][l], stride EP_STRIDE
#pragma unroll
    for (int mi = 0; mi < 2; mi++) {
#pragma unroll
        for (int f = 0; f < 8; f++) {
            int l  = ml + 16 * mi + ar;
            int oc = 8 * f + 2 * ac;
            ep[oc * EP_STRIDE + l]           = d[mi][f][0];
            ep[(oc + 1) * EP_STRIDE + l]     = d[mi][f][1];
            ep[oc * EP_STRIDE + l + 8]       = d[mi][f][2];
            ep[(oc + 1) * EP_STRIDE + l + 8] = d[mi][f][3];
        }
    }
    __syncthreads();

#pragma unroll
    for (int i = 0; i < 8; i++) {
        int oc  = wid * 8 + i;
        int goc = g * OPG + oc;
        float add = g_ctx[n * C_OUT + goc] + bias[goc];
        const float4* src = (const float4*)(ep + oc * EP_STRIDE);
        float4* dst = (float4*)(out + ((size_t)(n * C_OUT + goc)) * L_LEN + l0);
#pragma unroll
        for (int it = 0; it < 2; it++) {
            float4 v = src[lane + it * 32];
            v.x += add; v.y += add; v.z += add; v.w += add;
            dst[lane + it * 32] = v;
        }
    }
}

// ---------------------------------------------------------------------------
extern "C" void kernel_launch(void* const* d_in, const int* in_sizes, int n_in,
                              void* d_out, int out_size) {
    const float* x    = (const float*)d_in[0];  // (32, 256, 4096)
    const float* c    = (const float*)d_in[1];  // (32, 128)
    const float* w    = (const float*)d_in[2];  // (256, 64, 9)
    const float* cw   = (const float*)d_in[3];  // (256, 128)
    const float* bias = (const float*)d_in[4];  // (256,)
    float* out = (float*)d_out;                 // (32, 256, 4096)

    cudaFuncSetAttribute(conv_kernel, cudaFuncAttributeMaxDynamicSharedMemorySize, SM_TOTAL);

    prep_kernel<<<GROUPS * KW + 128, 256>>>(w, c, cw);
    dim3 grid(L_LEN / L_TILE, GROUPS, N_B);     // (16, 4, 32)
    conv_kernel<<<grid, NTHR, SM_TOTAL>>>(x, bias, out);
}

// round 7
// speedup vs baseline: 1.4156x; 1.0684x over previous
#include <cuda_runtime.h>
#include <cstdint>

// ---------------- problem constants ----------------
#define N_B    32
#define C_IN   256
#define L_LEN  4096
#define C_OUT  256
#define KW     9
#define GROUPS 4
#define CPG    64
#define OPG    64
#define C_DIM  128
#define PAD    4

#define L_TILE 256
#define NTHR   256                          // 8 warps; warp tile = 32 l x 64 oc
#define XS_STRIDE 264                       // words; %32==8 -> A-frag LDS conflict-free
#define EP_STRIDE 260                       // words; epilogue staging stride

// smem layout (bytes)
#define SM_XS    0                          // 64 x 264 f32 = 67,584 (aliased by epilogue)
#define SM_B     67584                      // 2 x 18,432 B double-buffered B blocks
#define SM_CTX   (SM_B + 2 * 18432)         // 64 floats ctx+bias
#define SM_TOTAL (SM_CTX + 256)             // 104,704 B (x2 CTA/SM = 209,408)

// ---------------- device scratch ----------------
__device__ float g_ctx[N_B * C_OUT];
// B tiles: per g: [s=8][k=9] blocks of 512 words (64oc x 8ic frag-ordered tf32)
__device__ unsigned int g_wt[GROUPS * 8 * KW * 512];

__device__ __forceinline__ uint32_t tf32rn(float f) {
    uint32_t r;
    asm("cvt.rna.tf32.f32 %0, %1;" : "=r"(r) : "f"(f));
    return r;
}
__device__ __forceinline__ uint32_t smem_u32(const void* p) {
    uint32_t a;
    asm("{ .reg .u64 t; cvta.to.shared.u64 t, %1; cvt.u32.u64 %0, t; }" : "=r"(a) : "l"(p));
    return a;
}
// cp.async with zfill: copies src_size bytes (0 or 16), zero-fills the rest
__device__ __forceinline__ void cp16z(uint32_t dst, const void* src, uint32_t src_size) {
    asm volatile("cp.async.cg.shared.global [%0], [%1], 16, %2;"
                 :: "r"(dst), "l"(src), "r"(src_size));
}
#define CP_COMMIT() asm volatile("cp.async.commit_group;" ::: "memory")
__device__ __forceinline__ void cp_wait(int n) {
    switch (n) {
        case 0: asm volatile("cp.async.wait_group 0;" ::: "memory"); break;
        case 1: asm volatile("cp.async.wait_group 1;" ::: "memory"); break;
        case 2: asm volatile("cp.async.wait_group 2;" ::: "memory"); break;
        case 3: asm volatile("cp.async.wait_group 3;" ::: "memory"); break;
        case 4: asm volatile("cp.async.wait_group 4;" ::: "memory"); break;
        case 5: asm volatile("cp.async.wait_group 5;" ::: "memory"); break;
        case 6: asm volatile("cp.async.wait_group 6;" ::: "memory"); break;
        default: asm volatile("cp.async.wait_group 7;" ::: "memory"); break;
    }
}

__device__ __forceinline__ void mma_tf32(float* d, const uint32_t* a, uint32_t b0, uint32_t b1) {
    asm("mma.sync.aligned.m16n8k8.row.col.f32.tf32.tf32.f32 "
        "{%0,%1,%2,%3}, {%4,%5,%6,%7}, {%8,%9}, {%0,%1,%2,%3};"
        : "+f"(d[0]), "+f"(d[1]), "+f"(d[2]), "+f"(d[3])
        : "r"(a[0]), "r"(a[1]), "r"(a[2]), "r"(a[3]), "r"(b0), "r"(b1));
}

// ---------------------------------------------------------------------------
// prep_kernel: blocks [0,36) -> weight fragment tiles ([g][s][k] blocks);
//              blocks [36,164) -> ctx GEMM.
// Within a 512-word (s,k) block: idx2 = (q*32+lane)*4 + r,
//   f = 2q + (r>>1); oc = 8f + (lane>>2); ic = 8s + (lane&3) + 4*(r&1)
// ---------------------------------------------------------------------------
__global__ void prep_kernel(const float* __restrict__ w,
                            const float* __restrict__ c,
                            const float* __restrict__ cw) {
    int bx = blockIdx.x, tid = threadIdx.x;
    if (bx < GROUPS * KW) {
        int g = bx / KW, k = bx - g * KW;
        for (int idx = tid; idx < 4096; idx += 256) {
            int r    = idx & 3;
            int lane = (idx >> 2) & 31;
            int q    = (idx >> 7) & 3;
            int s    = idx >> 9;
            int f    = 2 * q + (r >> 1);
            int oc   = 8 * f + (lane >> 2);
            int ic   = 8 * s + (lane & 3) + 4 * (r & 1);
            g_wt[(size_t)g * 36864 + (s * KW + k) * 512 + (q * 32 + lane) * 4 + r] =
                tf32rn(w[(size_t)(g * OPG + oc) * (CPG * KW) + ic * KW + k]);
        }
    } else {
        int o  = (bx - GROUPS * KW) * 64 + (tid >> 2);   // 0..8191
        int n  = o >> 8, oc = o & 255;
        const float* cr = c  + (size_t)n  * C_DIM + (tid & 3) * 32;
        const float* wr = cw + (size_t)oc * C_DIM + (tid & 3) * 32;
        float s = 0.f;
#pragma unroll 8
        for (int d = 0; d < 32; d++) s += cr[d] * wr[d];
        s += __shfl_down_sync(0xFFFFFFFFu, s, 2);
        s += __shfl_down_sync(0xFFFFFFFFu, s, 1);
        if ((tid & 3) == 0) g_ctx[o] = s;
    }
}

// ---------------------------------------------------------------------------
// conv_kernel: grouped conv as implicit GEMM (tf32 mma.sync, fp32 accum).
// Block (lt, g, n): 256 l x 64 oc, 8 warps; warp = 32 l x 64 oc.
// s-outer (ic-octets) / k-inner (taps); x streamed via per-octet cp.async.
// ---------------------------------------------------------------------------
__global__ void __launch_bounds__(NTHR, 2)
conv_kernel(const float* __restrict__ x, const float* __restrict__ bias,
            float* __restrict__ out) {
    extern __shared__ char smem[];
    const uint32_t sb = smem_u32(smem);
    uint32_t* xs = (uint32_t*)(smem + SM_XS);

    const int tid = threadIdx.x;
    const int wid = tid >> 5, lane = tid & 31;
    const int lt = blockIdx.x, g = blockIdx.y, n = blockIdx.z;
    const int l0 = lt * L_TILE;

    // ---- prologue: issue all 8 x ic-octets as separate cp.async groups ----
    {
        const float* xb = x + ((size_t)(n * C_IN + g * CPG)) * L_LEN + (l0 - PAD);
#pragma unroll 1
        for (int o = 0; o < 8; o++) {
            for (int i = tid; i < 528; i += NTHR) {
                int row = i / 66, c = i - row * 66;       // 66 16B-chunks per row
                int gl = l0 - PAD + 4 * c;                // first float of chunk
                uint32_t sz = (gl >= 0 && gl <= L_LEN - 4) ? 16u : 0u;
                uint32_t dst = sb + ((8 * o + row) * XS_STRIDE + 4 * c) * 4;
                cp16z(dst, xb + (size_t)(8 * o + row) * L_LEN + 4 * c, sz);
            }
            CP_COMMIT();
        }
    }
    // ctx + bias for this (n, g) into smem
    if (tid < OPG) {
        int goc = g * OPG + tid;
        ((float*)(smem + SM_CTX))[tid] = g_ctx[n * C_OUT + goc] + bias[goc];
    }

    // ---- accumulators: warp tile 32 l x 64 oc = 2 (mi) x 8 (f) frags ----
    float d[2][8][4];
#pragma unroll
    for (int mi = 0; mi < 2; mi++)
#pragma unroll
        for (int f = 0; f < 8; f++)
#pragma unroll
            for (int r = 0; r < 4; r++) d[mi][f][r] = 0.f;

    const int ml = wid * 32;
    const int ar = lane >> 5 ? 0 : (lane >> 2);   // lane>>2 (0..7)
    const int ac = lane & 3;

#pragma unroll 1
    for (int s = 0; s < 8; s++) {
        // -- load B block s (18,432 B = 1152 uint4) from gmem into registers --
        const uint4* bg = (const uint4*)(g_wt + (size_t)g * 36864 + s * (KW * 512));
        uint4 br0 = bg[tid];
        uint4 br1 = bg[tid + 256];
        uint4 br2 = bg[tid + 512];
        uint4 br3 = bg[tid + 768];
        uint4 br4 = (tid < 128) ? bg[tid + 1024] : make_uint4(0, 0, 0, 0);

        // -- wait for x octets 0..s --
        cp_wait(7 - s);

        // -- store B into parity buffer (other parity still in use pre-sync? no:
        //    all warps are past s-1's compute only after the barrier below;
        //    parity s&1 was last used in s-2, retired by s-1's barrier) --
        {
            uint4* bs = (uint4*)(smem + SM_B + (s & 1) * 18432);
            bs[tid] = br0; bs[tid + 256] = br1; bs[tid + 512] = br2; bs[tid + 768] = br3;
            if (tid < 128) bs[tid + 1024] = br4;
        }
        __syncthreads();

        const char* bb = smem + SM_B + (s & 1) * 18432;
        const uint32_t* xrow0 = xs + (s * 8 + ac) * XS_STRIDE + (ml + ar);
        const uint32_t* xrow4 = xrow0 + 4 * XS_STRIDE;

#pragma unroll
        for (int k = 0; k < KW; k++) {
            // A fragments: 8 LDS.32 (conflict-free) + tf32 round in registers
            uint32_t a[2][4];
#pragma unroll
            for (int mi = 0; mi < 2; mi++) {
                a[mi][0] = tf32rn(__uint_as_float(xrow0[k + mi * 16]));
                a[mi][1] = tf32rn(__uint_as_float(xrow0[k + mi * 16 + 8]));
                a[mi][2] = tf32rn(__uint_as_float(xrow4[k + mi * 16]));
                a[mi][3] = tf32rn(__uint_as_float(xrow4[k + mi * 16 + 8]));
            }
            // B fragments: 4 conflict-free lds.128
            uint4 bq[4];
            {
                const uint4* bsrc = (const uint4*)(bb + k * 2048) + lane;
#pragma unroll
                for (int q = 0; q < 4; q++) bq[q] = bsrc[q * 32];
            }
#pragma unroll
            for (int mi = 0; mi < 2; mi++) {
#pragma unroll
                for (int q = 0; q < 4; q++) {
                    mma_tf32(d[mi][2 * q],     a[mi], bq[q].x, bq[q].y);
                    mma_tf32(d[mi][2 * q + 1], a[mi], bq[q].z, bq[q].w);
                }
            }
        }
        __syncthreads();   // retire this s before next s overwrites other parity
    }

    // ---- epilogue: stage through smem (alias xs), coalesced float4 out ----
    float* ep = (float*)(smem + SM_XS);   // [oc][l], stride EP_STRIDE
#pragma unroll
    for (int mi = 0; mi < 2; mi++) {
#pragma unroll
        for (int f = 0; f < 8; f++) {
            int l  = ml + 16 * mi + (lane >> 2);
            int oc = 8 * f + 2 * ac;
            ep[oc * EP_STRIDE + l]           = d[mi][f][0];
            ep[(oc + 1) * EP_STRIDE + l]     = d[mi][f][1];
            ep[oc * EP_STRIDE + l + 8]       = d[mi][f][2];
            ep[(oc + 1) * EP_STRIDE + l + 8] = d[mi][f][3];
        }
    }
    __syncthreads();

    const float* sadd = (const float*)(smem + SM_CTX);
#pragma unroll
    for (int i = 0; i < 8; i++) {
        int oc  = wid * 8 + i;
        int goc = g * OPG + oc;
        float add = sadd[oc];
        const float4* src = (const float4*)(ep + oc * EP_STRIDE);
        float4* dst = (float4*)(out + ((size_t)(n * C_OUT + goc)) * L_LEN + l0);
#pragma unroll
        for (int it = 0; it < 2; it++) {
            float4 v = src[lane + it * 32];
            v.x += add; v.y += add; v.z += add; v.w += add;
            dst[lane + it * 32] = v;
        }
    }
}

// ---------------------------------------------------------------------------
extern "C" void kernel_launch(void* const* d_in, const int* in_sizes, int n_in,
                              void* d_out, int out_size) {
    const float* x    = (const float*)d_in[0];  // (32, 256, 4096)
    const float* c    = (const float*)d_in[1];  // (32, 128)
    const float* w    = (const float*)d_in[2];  // (256, 64, 9)
    const float* cw   = (const float*)d_in[3];  // (256, 128)
    const float* bias = (const float*)d_in[4];  // (256,)
    float* out = (float*)d_out;                 // (32, 256, 4096)

    cudaFuncSetAttribute(conv_kernel, cudaFuncAttributeMaxDynamicSharedMemorySize, SM_TOTAL);

    prep_kernel<<<GROUPS * KW + 128, 256>>>(w, c, cw);
    dim3 grid(L_LEN / L_TILE, GROUPS, N_B);     // (16, 4, 32)
    conv_kernel<<<grid, NTHR, SM_TOTAL>>>(x, bias, out);
}

// round 8
// speedup vs baseline: 1.5644x; 1.1051x over previous
#include <cuda_runtime.h>
#include <cstdint>

// ---------------- problem constants ----------------
#define N_B    32
#define C_IN   256
#define L_LEN  4096
#define C_OUT  256
#define KW     9
#define GROUPS 4
#define CPG    64
#define OPG    64
#define C_DIM  128
#define PAD    4

#define L_TILE 256
#define NTHR   256                          // 8 warps; warp tile = 32 l x 64 oc
#define XS_STRIDE 264                       // words; %32==8 -> A-frag LDS conflict-free
#define EP_STRIDE 260                       // words; epilogue staging stride

// smem layout (bytes): 3-slot rings for x octets and B blocks
#define X_SLOT_B  (8 * XS_STRIDE * 4)       // 8,448 B per x octet slot
#define B_SLOT_B  18432                     // 9 taps x 512 words per B block
#define SM_X      0                         // 3 x 8,448  = 25,344
#define SM_B      (3 * X_SLOT_B)            // 3 x 18,432 = 55,296
#define SM_CTX    (SM_B + 3 * B_SLOT_B)     // 80,640
#define SM_TOTAL  (SM_CTX + 256)            // 80,896 B (x2 CTA/SM = 161,792)
// epilogue aliases [0, 66560) -- safe after final barrier

// ---------------- device scratch ----------------
__device__ float g_ctx[N_B * C_OUT];
// B tiles: per g: [s=8][k=9] blocks of 512 words (64oc x 8ic frag-ordered tf32)
__device__ unsigned int g_wt[GROUPS * 8 * KW * 512];

__device__ __forceinline__ uint32_t tf32rn(float f) {
    uint32_t r;
    asm("cvt.rna.tf32.f32 %0, %1;" : "=r"(r) : "f"(f));
    return r;
}
__device__ __forceinline__ uint32_t smem_u32(const void* p) {
    uint32_t a;
    asm("{ .reg .u64 t; cvta.to.shared.u64 t, %1; cvt.u32.u64 %0, t; }" : "=r"(a) : "l"(p));
    return a;
}
__device__ __forceinline__ void cp16(uint32_t dst, const void* src) {
    asm volatile("cp.async.cg.shared.global [%0], [%1], 16;" :: "r"(dst), "l"(src));
}
// zfill form: copies src_size (0 or 16) bytes, zero-fills remainder
__device__ __forceinline__ void cp16z(uint32_t dst, const void* src, uint32_t src_size) {
    asm volatile("cp.async.cg.shared.global [%0], [%1], 16, %2;"
                 :: "r"(dst), "l"(src), "r"(src_size));
}
#define CP_COMMIT() asm volatile("cp.async.commit_group;" ::: "memory")
#define CP_WAIT2()  asm volatile("cp.async.wait_group 2;" ::: "memory")

__device__ __forceinline__ void mma_tf32(float* d, const uint32_t* a, uint32_t b0, uint32_t b1) {
    asm("mma.sync.aligned.m16n8k8.row.col.f32.tf32.tf32.f32 "
        "{%0,%1,%2,%3}, {%4,%5,%6,%7}, {%8,%9}, {%0,%1,%2,%3};"
        : "+f"(d[0]), "+f"(d[1]), "+f"(d[2]), "+f"(d[3])
        : "r"(a[0]), "r"(a[1]), "r"(a[2]), "r"(a[3]), "r"(b0), "r"(b1));
}

// ---------------------------------------------------------------------------
// prep_kernel: blocks [0,36) -> weight fragment tiles ([g][s][k] blocks);
//              blocks [36,164) -> ctx GEMM.
// ---------------------------------------------------------------------------
__global__ void prep_kernel(const float* __restrict__ w,
                            const float* __restrict__ c,
                            const float* __restrict__ cw) {
    int bx = blockIdx.x, tid = threadIdx.x;
    if (bx < GROUPS * KW) {
        int g = bx / KW, k = bx - g * KW;
        for (int idx = tid; idx < 4096; idx += 256) {
            int r    = idx & 3;
            int lane = (idx >> 2) & 31;
            int q    = (idx >> 7) & 3;
            int s    = idx >> 9;
            int f    = 2 * q + (r >> 1);
            int oc   = 8 * f + (lane >> 2);
            int ic   = 8 * s + (lane & 3) + 4 * (r & 1);
            g_wt[(size_t)g * 36864 + (s * KW + k) * 512 + (q * 32 + lane) * 4 + r] =
                tf32rn(w[(size_t)(g * OPG + oc) * (CPG * KW) + ic * KW + k]);
        }
    } else {
        int o  = (bx - GROUPS * KW) * 64 + (tid >> 2);   // 0..8191
        int n  = o >> 8, oc = o & 255;
        const float* cr = c  + (size_t)n  * C_DIM + (tid & 3) * 32;
        const float* wr = cw + (size_t)oc * C_DIM + (tid & 3) * 32;
        float s = 0.f;
#pragma unroll 8
        for (int d = 0; d < 32; d++) s += cr[d] * wr[d];
        s += __shfl_down_sync(0xFFFFFFFFu, s, 2);
        s += __shfl_down_sync(0xFFFFFFFFu, s, 1);
        if ((tid & 3) == 0) g_ctx[o] = s;
    }
}

// ---------------------------------------------------------------------------
// conv_kernel: grouped conv as implicit GEMM (tf32 mma.sync, fp32 accum).
// Block (lt, g, n): 256 l x 64 oc, 8 warps; warp = 32 l x 64 oc.
// s-outer (ic octets); x AND B streamed via one interleaved cp.async FIFO,
// 2 iterations ahead, into 3-slot smem rings. One barrier per iteration.
// ---------------------------------------------------------------------------
__global__ void __launch_bounds__(NTHR, 2)
conv_kernel(const float* __restrict__ x, const float* __restrict__ bias,
            float* __restrict__ out) {
    extern __shared__ char smem[];
    const uint32_t sb = smem_u32(smem);

    const int tid = threadIdx.x;
    const int wid = tid >> 5, lane = tid & 31;
    const int lt = blockIdx.x, g = blockIdx.y, n = blockIdx.z;
    const int l0 = lt * L_TILE;

    const float* xb = x + ((size_t)(n * C_IN + g * CPG)) * L_LEN + (l0 - PAD);
    const char*  bw = (const char*)(g_wt + (size_t)g * 36864);

    // --- issue helpers (lambdas keep the FIFO discipline in one place) ---
    auto issue_x = [&](int o) {                    // x octet o -> slot o%3
        uint32_t base = sb + SM_X + (o % 3) * X_SLOT_B;
#pragma unroll
        for (int it = 0; it < 3; it++) {           // 528 chunks, 256 threads
            int i = tid + it * NTHR;
            if (i < 528) {
                int row = i / 66, c = i - row * 66;
                int gl = l0 - PAD + 4 * c;
                uint32_t sz = (gl >= 0 && gl <= L_LEN - 4) ? 16u : 0u;
                cp16z(base + (row * XS_STRIDE + 4 * c) * 4,
                      xb + (size_t)(8 * o + row) * L_LEN + 4 * c, sz);
            }
        }
    };
    auto issue_b = [&](int o) {                    // B block o -> slot o%3
        uint32_t base = sb + SM_B + (o % 3) * B_SLOT_B;
        const char* src = bw + (size_t)o * B_SLOT_B;
#pragma unroll
        for (int it = 0; it < 4; it++)
            cp16(base + (tid + it * NTHR) * 16, src + (size_t)(tid + it * NTHR) * 16);
        if (tid < 128) cp16(base + (tid + 1024) * 16, src + (size_t)(tid + 1024) * 16);
    };

    // ---- prologue: groups x0, B0, x1, B1 ----
    issue_x(0); CP_COMMIT();
    issue_b(0); CP_COMMIT();
    issue_x(1); CP_COMMIT();
    issue_b(1); CP_COMMIT();

    // ctx + bias for this (n, g) into smem
    if (tid < OPG) {
        int goc = g * OPG + tid;
        ((float*)(smem + SM_CTX))[tid] = g_ctx[n * C_OUT + goc] + bias[goc];
    }

    // ---- accumulators: warp tile 32 l x 64 oc = 2 (mi) x 8 (f) frags ----
    float d[2][8][4];
#pragma unroll
    for (int mi = 0; mi < 2; mi++)
#pragma unroll
        for (int f = 0; f < 8; f++)
#pragma unroll
            for (int r = 0; r < 4; r++) d[mi][f][r] = 0.f;

    const int ml = wid * 32;
    const int ar = lane >> 2;      // a-frag row (0..7)
    const int ac = lane & 3;       // a-frag col (ic offset)

#pragma unroll 1
    for (int s = 0; s < 8; s++) {
        // x(s), B(s) landed when at most 2 commit-pairs (s+1, s+2) are pending
        CP_WAIT2();
        __syncthreads();           // visibility of all threads' copies + ring safety

        // issue s+2 (empty commits for s >= 6 keep the FIFO arithmetic uniform)
        if (s + 2 < 8) issue_x(s + 2);
        CP_COMMIT();
        if (s + 2 < 8) issue_b(s + 2);
        CP_COMMIT();

        const uint32_t* xslot = (const uint32_t*)(smem + SM_X + (s % 3) * X_SLOT_B);
        const char*     bbslt = smem + SM_B + (s % 3) * B_SLOT_B;
        const uint32_t* xrow0 = xslot + ac * XS_STRIDE + (ml + ar);
        const uint32_t* xrow4 = xrow0 + 4 * XS_STRIDE;

#pragma unroll
        for (int k = 0; k < KW; k++) {
            // A fragments: 8 conflict-free LDS.32 + tf32 round
            uint32_t a[2][4];
#pragma unroll
            for (int mi = 0; mi < 2; mi++) {
                a[mi][0] = tf32rn(__uint_as_float(xrow0[k + mi * 16]));
                a[mi][1] = tf32rn(__uint_as_float(xrow0[k + mi * 16 + 8]));
                a[mi][2] = tf32rn(__uint_as_float(xrow4[k + mi * 16]));
                a[mi][3] = tf32rn(__uint_as_float(xrow4[k + mi * 16 + 8]));
            }
            // B fragments: 4 conflict-free LDS.128
            uint4 bq[4];
            {
                const uint4* bsrc = (const uint4*)(bbslt + k * 2048) + lane;
#pragma unroll
                for (int q = 0; q < 4; q++) bq[q] = bsrc[q * 32];
            }
#pragma unroll
            for (int mi = 0; mi < 2; mi++) {
#pragma unroll
                for (int q = 0; q < 4; q++) {
                    mma_tf32(d[mi][2 * q],     a[mi], bq[q].x, bq[q].y);
                    mma_tf32(d[mi][2 * q + 1], a[mi], bq[q].z, bq[q].w);
                }
            }
        }
    }
    __syncthreads();   // all compute done before epilogue clobbers the rings

    // ---- epilogue: stage through smem (alias ring region), coalesced out ----
    float* ep = (float*)smem;             // [oc][l], stride EP_STRIDE
#pragma unroll
    for (int mi = 0; mi < 2; mi++) {
#pragma unroll
        for (int f = 0; f < 8; f++) {
            int l  = ml + 16 * mi + ar;
            int oc = 8 * f + 2 * ac;
            ep[oc * EP_STRIDE + l]           = d[mi][f][0];
            ep[(oc + 1) * EP_STRIDE + l]     = d[mi][f][1];
            ep[oc * EP_STRIDE + l + 8]       = d[mi][f][2];
            ep[(oc + 1) * EP_STRIDE + l + 8] = d[mi][f][3];
        }
    }
    __syncthreads();

    const float* sadd = (const float*)(smem + SM_CTX);
#pragma unroll
    for (int i = 0; i < 8; i++) {
        int oc  = wid * 8 + i;
        int goc = g * OPG + oc;
        float add = sadd[oc];
        const float4* src = (const float4*)(ep + oc * EP_STRIDE);
        float4* dst = (float4*)(out + ((size_t)(n * C_OUT + goc)) * L_LEN + l0);
#pragma unroll
        for (int it = 0; it < 2; it++) {
            float4 v = src[lane + it * 32];
            v.x += add; v.y += add; v.z += add; v.w += add;
            dst[lane + it * 32] = v;
        }
    }
}

// ---------------------------------------------------------------------------
extern "C" void kernel_launch(void* const* d_in, const int* in_sizes, int n_in,
                              void* d_out, int out_size) {
    const float* x    = (const float*)d_in[0];  // (32, 256, 4096)
    const float* c    = (const float*)d_in[1];  // (32, 128)
    const float* w    = (const float*)d_in[2];  // (256, 64, 9)
    const float* cw   = (const float*)d_in[3];  // (256, 128)
    const float* bias = (const float*)d_in[4];  // (256,)
    float* out = (float*)d_out;                 // (32, 256, 4096)

    cudaFuncSetAttribute(conv_kernel, cudaFuncAttributeMaxDynamicSharedMemorySize, SM_TOTAL);

    prep_kernel<<<GROUPS * KW + 128, 256>>>(w, c, cw);
    dim3 grid(L_LEN / L_TILE, GROUPS, N_B);     // (16, 4, 32)
    conv_kernel<<<grid, NTHR, SM_TOTAL>>>(x, bias, out);
}

// round 9
// speedup vs baseline: 1.6464x; 1.0524x over previous
#include <cuda_runtime.h>
#include <cstdint>

// ---------------- problem constants ----------------
#define N_B    32
#define C_IN   256
#define L_LEN  4096
#define C_OUT  256
#define KW     9
#define GROUPS 4
#define CPG    64
#define OPG    64
#define C_DIM  128
#define PAD    4

#define L_TILE 256
#define NTHR   256                          // 8 warps; warp tile = 32 l x 64 oc
#define XS_STRIDE 264                       // words; %32==8 -> A-frag LDS conflict-free
#define EP_STRIDE 260                       // words; epilogue staging stride

// smem layout (bytes): 3-slot rings for x octets and B blocks
#define X_SLOT_B  (8 * XS_STRIDE * 4)       // 8,448 B per x octet slot
#define B_SLOT_B  18432                     // 9 taps x 512 words per B block
#define SM_X      0                         // 3 x 8,448  = 25,344
#define SM_B      (3 * X_SLOT_B)            // 3 x 18,432 = 55,296
#define SM_CTX    (SM_B + 3 * B_SLOT_B)     // 80,640
#define SM_TOTAL  (SM_CTX + 256)            // 80,896 B (x2 CTA/SM = 161,792)
// epilogue aliases [0, 66560) -- safe after final barrier

// ---------------- device scratch ----------------
__device__ float g_ctx[N_B * C_OUT];
// B tiles: per g: [s=8][k=9] blocks of 512 words (64oc x 8ic frag-ordered tf32)
__device__ unsigned int g_wt[GROUPS * 8 * KW * 512];

__device__ __forceinline__ uint32_t tf32rn(float f) {
    uint32_t r;
    asm("cvt.rna.tf32.f32 %0, %1;" : "=r"(r) : "f"(f));
    return r;
}
__device__ __forceinline__ uint32_t smem_u32(const void* p) {
    uint32_t a;
    asm("{ .reg .u64 t; cvta.to.shared.u64 t, %1; cvt.u32.u64 %0, t; }" : "=r"(a) : "l"(p));
    return a;
}
__device__ __forceinline__ void cp16(uint32_t dst, const void* src) {
    asm volatile("cp.async.cg.shared.global [%0], [%1], 16;" :: "r"(dst), "l"(src));
}
// zfill form: copies src_size (0 or 16) bytes, zero-fills remainder
__device__ __forceinline__ void cp16z(uint32_t dst, const void* src, uint32_t src_size) {
    asm volatile("cp.async.cg.shared.global [%0], [%1], 16, %2;"
                 :: "r"(dst), "l"(src), "r"(src_size));
}
#define CP_COMMIT() asm volatile("cp.async.commit_group;" ::: "memory")
#define CP_WAIT2()  asm volatile("cp.async.wait_group 2;" ::: "memory")

__device__ __forceinline__ void mma_tf32(float* d, const uint32_t* a, uint32_t b0, uint32_t b1) {
    asm("mma.sync.aligned.m16n8k8.row.col.f32.tf32.tf32.f32 "
        "{%0,%1,%2,%3}, {%4,%5,%6,%7}, {%8,%9}, {%0,%1,%2,%3};"
        : "+f"(d[0]), "+f"(d[1]), "+f"(d[2]), "+f"(d[3])
        : "r"(a[0]), "r"(a[1]), "r"(a[2]), "r"(a[3]), "r"(b0), "r"(b1));
}

// ---------------------------------------------------------------------------
// prep_kernel: blocks [0,36) -> weight fragment tiles ([g][s][k] blocks);
//              blocks [36,164) -> ctx GEMM.
// ---------------------------------------------------------------------------
__global__ void prep_kernel(const float* __restrict__ w,
                            const float* __restrict__ c,
                            const float* __restrict__ cw) {
    int bx = blockIdx.x, tid = threadIdx.x;
    if (bx < GROUPS * KW) {
        int g = bx / KW, k = bx - g * KW;
        for (int idx = tid; idx < 4096; idx += 256) {
            int r    = idx & 3;
            int lane = (idx >> 2) & 31;
            int q    = (idx >> 7) & 3;
            int s    = idx >> 9;
            int f    = 2 * q + (r >> 1);
            int oc   = 8 * f + (lane >> 2);
            int ic   = 8 * s + (lane & 3) + 4 * (r & 1);
            g_wt[(size_t)g * 36864 + (s * KW + k) * 512 + (q * 32 + lane) * 4 + r] =
                tf32rn(w[(size_t)(g * OPG + oc) * (CPG * KW) + ic * KW + k]);
        }
    } else {
        int o  = (bx - GROUPS * KW) * 64 + (tid >> 2);   // 0..8191
        int n  = o >> 8, oc = o & 255;
        const float* cr = c  + (size_t)n  * C_DIM + (tid & 3) * 32;
        const float* wr = cw + (size_t)oc * C_DIM + (tid & 3) * 32;
        float s = 0.f;
#pragma unroll 8
        for (int d = 0; d < 32; d++) s += cr[d] * wr[d];
        s += __shfl_down_sync(0xFFFFFFFFu, s, 2);
        s += __shfl_down_sync(0xFFFFFFFFu, s, 1);
        if ((tid & 3) == 0) g_ctx[o] = s;
    }
}

// ---------------------------------------------------------------------------
// conv_kernel: grouped conv as implicit GEMM (tf32 mma.sync, fp32 accum).
// Block (lt, g, n): 256 l x 64 oc, 8 warps; warp = 32 l x 64 oc.
// s-outer (ic octets); x AND B streamed via one interleaved cp.async FIFO,
// 2 iterations ahead, into 3-slot smem rings. One barrier per iteration.
// A operands fed as raw fp32 (HW tf32 truncation) -- no cvt in mainloop.
// ---------------------------------------------------------------------------
__global__ void __launch_bounds__(NTHR, 2)
conv_kernel(const float* __restrict__ x, const float* __restrict__ bias,
            float* __restrict__ out) {
    extern __shared__ char smem[];
    const uint32_t sb = smem_u32(smem);

    const int tid = threadIdx.x;
    const int wid = tid >> 5, lane = tid & 31;
    const int lt = blockIdx.x, g = blockIdx.y, n = blockIdx.z;
    const int l0 = lt * L_TILE;

    const float* xb = x + ((size_t)(n * C_IN + g * CPG)) * L_LEN + (l0 - PAD);
    const char*  bw = (const char*)(g_wt + (size_t)g * 36864);

    // --- issue helpers ---
    auto issue_x = [&](int o) {                    // x octet o -> slot o%3
        uint32_t base = sb + SM_X + (o % 3) * X_SLOT_B;
#pragma unroll
        for (int it = 0; it < 3; it++) {           // 528 chunks, 256 threads
            int i = tid + it * NTHR;
            if (i < 528) {
                int row = i / 66, c = i - row * 66;
                int gl = l0 - PAD + 4 * c;
                uint32_t sz = (gl >= 0 && gl <= L_LEN - 4) ? 16u : 0u;
                cp16z(base + (row * XS_STRIDE + 4 * c) * 4,
                      xb + (size_t)(8 * o + row) * L_LEN + 4 * c, sz);
            }
        }
    };
    auto issue_b = [&](int o) {                    // B block o -> slot o%3
        uint32_t base = sb + SM_B + (o % 3) * B_SLOT_B;
        const char* src = bw + (size_t)o * B_SLOT_B;
#pragma unroll
        for (int it = 0; it < 4; it++)
            cp16(base + (tid + it * NTHR) * 16, src + (size_t)(tid + it * NTHR) * 16);
        if (tid < 128) cp16(base + (tid + 1024) * 16, src + (size_t)(tid + 1024) * 16);
    };

    // ---- prologue: groups x0, B0, x1, B1 ----
    issue_x(0); CP_COMMIT();
    issue_b(0); CP_COMMIT();
    issue_x(1); CP_COMMIT();
    issue_b(1); CP_COMMIT();

    // ctx + bias for this (n, g) into smem
    if (tid < OPG) {
        int goc = g * OPG + tid;
        ((float*)(smem + SM_CTX))[tid] = g_ctx[n * C_OUT + goc] + bias[goc];
    }

    // ---- accumulators: warp tile 32 l x 64 oc = 2 (mi) x 8 (f) frags ----
    float d[2][8][4];
#pragma unroll
    for (int mi = 0; mi < 2; mi++)
#pragma unroll
        for (int f = 0; f < 8; f++)
#pragma unroll
            for (int r = 0; r < 4; r++) d[mi][f][r] = 0.f;

    const int ml = wid * 32;
    const int ar = lane >> 2;      // a-frag row (0..7)
    const int ac = lane & 3;       // a-frag col (ic offset)

#pragma unroll 1
    for (int s = 0; s < 8; s++) {
        // x(s), B(s) landed when at most 2 commit-pairs (s+1, s+2) are pending
        CP_WAIT2();
        __syncthreads();           // visibility + ring-slot safety

        // issue s+2 (empty commits for s >= 6 keep FIFO arithmetic uniform)
        if (s + 2 < 8) issue_x(s + 2);
        CP_COMMIT();
        if (s + 2 < 8) issue_b(s + 2);
        CP_COMMIT();

        const uint32_t* xslot = (const uint32_t*)(smem + SM_X + (s % 3) * X_SLOT_B);
        const char*     bbslt = smem + SM_B + (s % 3) * B_SLOT_B;
        const uint32_t* xrow0 = xslot + ac * XS_STRIDE + (ml + ar);
        const uint32_t* xrow4 = xrow0 + 4 * XS_STRIDE;

#pragma unroll
        for (int k = 0; k < KW; k++) {
            // A fragments: 8 conflict-free LDS.32, raw fp32 (HW truncates to tf32)
            uint32_t a[2][4];
#pragma unroll
            for (int mi = 0; mi < 2; mi++) {
                a[mi][0] = xrow0[k + mi * 16];
                a[mi][1] = xrow0[k + mi * 16 + 8];
                a[mi][2] = xrow4[k + mi * 16];
                a[mi][3] = xrow4[k + mi * 16 + 8];
            }
            // B fragments: 4 conflict-free LDS.128
            uint4 bq[4];
            {
                const uint4* bsrc = (const uint4*)(bbslt + k * 2048) + lane;
#pragma unroll
                for (int q = 0; q < 4; q++) bq[q] = bsrc[q * 32];
            }
#pragma unroll
            for (int mi = 0; mi < 2; mi++) {
#pragma unroll
                for (int q = 0; q < 4; q++) {
                    mma_tf32(d[mi][2 * q],     a[mi], bq[q].x, bq[q].y);
                    mma_tf32(d[mi][2 * q + 1], a[mi], bq[q].z, bq[q].w);
                }
            }
        }
    }
    __syncthreads();   // all compute done before epilogue clobbers the rings

    // ---- epilogue: stage through smem (alias ring region), coalesced out ----
    float* ep = (float*)smem;             // [oc][l], stride EP_STRIDE
#pragma unroll
    for (int mi = 0; mi < 2; mi++) {
#pragma unroll
        for (int f = 0; f < 8; f++) {
            int l  = ml + 16 * mi + ar;
            int oc = 8 * f + 2 * ac;
            ep[oc * EP_STRIDE + l]           = d[mi][f][0];
            ep[(oc + 1) * EP_STRIDE + l]     = d[mi][f][1];
            ep[oc * EP_STRIDE + l + 8]       = d[mi][f][2];
            ep[(oc + 1) * EP_STRIDE + l + 8] = d[mi][f][3];
        }
    }
    __syncthreads();

    const float* sadd = (const float*)(smem + SM_CTX);
#pragma unroll
    for (int i = 0; i < 8; i++) {
        int oc  = wid * 8 + i;
        int goc = g * OPG + oc;
        float add = sadd[oc];
        const float4* src = (const float4*)(ep + oc * EP_STRIDE);
        float4* dst = (float4*)(out + ((size_t)(n * C_OUT + goc)) * L_LEN + l0);
#pragma unroll
        for (int it = 0; it < 2; it++) {
            float4 v = src[lane + it * 32];
            v.x += add; v.y += add; v.z += add; v.w += add;
            dst[lane + it * 32] = v;
        }
    }
}

// ---------------------------------------------------------------------------
extern "C" void kernel_launch(void* const* d_in, const int* in_sizes, int n_in,
                              void* d_out, int out_size) {
    const float* x    = (const float*)d_in[0];  // (32, 256, 4096)
    const float* c    = (const float*)d_in[1];  // (32, 128)
    const float* w    = (const float*)d_in[2];  // (256, 64, 9)
    const float* cw   = (const float*)d_in[3];  // (256, 128)
    const float* bias = (const float*)d_in[4];  // (256,)
    float* out = (float*)d_out;                 // (32, 256, 4096)

    cudaFuncSetAttribute(conv_kernel, cudaFuncAttributeMaxDynamicSharedMemorySize, SM_TOTAL);

    prep_kernel<<<GROUPS * KW + 128, 256>>>(w, c, cw);
    dim3 grid(L_LEN / L_TILE, GROUPS, N_B);     // (16, 4, 32)
    conv_kernel<<<grid, NTHR, SM_TOTAL>>>(x, bias, out);
}

// round 10
// speedup vs baseline: 2.4274x; 1.4743x over previous
#include <cuda_runtime.h>
#include <cstdint>

// ---------------- problem constants ----------------
#define N_B    32
#define C_IN   256
#define L_LEN  4096
#define C_OUT  256
#define KW     9
#define GROUPS 4
#define CPG    64
#define OPG    64
#define C_DIM  128
#define PAD    4

#define L_TILE 256
#define NTHR   256                          // 8 warps; warp tile = 32 l x 64 oc
#define XS_STRIDE 276                       // words; %16==4 -> A-frag LDS conflict-free
#define EP_STRIDE 260                       // words; epilogue staging stride

// smem layout (bytes): 3-slot rings; chunk = 16 ic rows
#define X_SLOT_B  (16 * XS_STRIDE * 4)      // 17,664 B per x chunk slot (fp32)
#define B_SLOT_B  18432                     // 9 taps x 512 fp16x2 words per chunk
#define SM_X      0                         // 3 x 17,664 = 52,992
#define SM_B      (3 * X_SLOT_B)            // 3 x 18,432 = 55,296
#define SM_CTX    (SM_B + 3 * B_SLOT_B)     // 108,288
#define SM_TOTAL  (SM_CTX + 256)            // 108,544 B (x2 CTA/SM)
// epilogue aliases [0, 66,560) of the rings -- dead after final barrier

// ---------------- device scratch ----------------
__device__ float g_ctx[N_B * C_OUT];
// B tiles: per g: [t=4][k=9] blocks of 512 fp16x2 words, m16n8k16 frag order
__device__ unsigned int g_wt[GROUPS * 4 * KW * 512];

__device__ __forceinline__ uint32_t smem_u32(const void* p) {
    uint32_t a;
    asm("{ .reg .u64 t; cvta.to.shared.u64 t, %1; cvt.u32.u64 %0, t; }" : "=r"(a) : "l"(p));
    return a;
}
// pack two f32 -> fp16x2 (lo = second operand), round-to-nearest
__device__ __forceinline__ uint32_t packh2(float hi, float lo) {
    uint32_t r;
    asm("cvt.rn.f16x2.f32 %0, %1, %2;" : "=r"(r) : "f"(hi), "f"(lo));
    return r;
}
__device__ __forceinline__ void cp16(uint32_t dst, const void* src) {
    asm volatile("cp.async.cg.shared.global [%0], [%1], 16;" :: "r"(dst), "l"(src));
}
__device__ __forceinline__ void cp16z(uint32_t dst, const void* src, uint32_t src_size) {
    asm volatile("cp.async.cg.shared.global [%0], [%1], 16, %2;"
                 :: "r"(dst), "l"(src), "r"(src_size));
}
#define CP_COMMIT() asm volatile("cp.async.commit_group;" ::: "memory")
#define CP_WAIT2()  asm volatile("cp.async.wait_group 2;" ::: "memory")

__device__ __forceinline__ void mma_f16(float* d, const uint32_t* a, uint32_t b0, uint32_t b1) {
    asm("mma.sync.aligned.m16n8k16.row.col.f32.f16.f16.f32 "
        "{%0,%1,%2,%3}, {%4,%5,%6,%7}, {%8,%9}, {%0,%1,%2,%3};"
        : "+f"(d[0]), "+f"(d[1]), "+f"(d[2]), "+f"(d[3])
        : "r"(a[0]), "r"(a[1]), "r"(a[2]), "r"(a[3]), "r"(b0), "r"(b1));
}

// ---------------------------------------------------------------------------
// prep_kernel: blocks [0,36) -> fp16x2 B fragment tiles; [36,164) -> ctx GEMM.
// Per (g,k): 2048 fp16x2 words. word idx = (t*9+k)*512 + qq*128 + lane*4 + qlo*2 + r
//   q = 2*qq+qlo; oc = 8q + (lane>>2); ic = 16t + 2*(lane&3) + 8r, pair (ic, ic+1)
// ---------------------------------------------------------------------------
__global__ void prep_kernel(const float* __restrict__ w,
                            const float* __restrict__ c,
                            const float* __restrict__ cw) {
    int bx = blockIdx.x, tid = threadIdx.x;
    if (bx < GROUPS * KW) {
        int g = bx / KW, k = bx - g * KW;
        for (int idx = tid; idx < 2048; idx += 256) {
            int r    = idx & 1;
            int qlo  = (idx >> 1) & 1;
            int lane = (idx >> 2) & 31;
            int qq   = (idx >> 7) & 3;
            int t    = idx >> 9;
            int oc   = 8 * (2 * qq + qlo) + (lane >> 2);
            int ic   = 16 * t + 2 * (lane & 3) + 8 * r;
            const float* wr = w + (size_t)(g * OPG + oc) * (CPG * KW) + k;
            float lo = wr[ic * KW];
            float hi = wr[(ic + 1) * KW];
            g_wt[(size_t)g * 18432 + (t * KW + k) * 512 +
                 (qq * 128 + lane * 4 + qlo * 2 + r)] = packh2(hi, lo);
        }
    } else {
        int o  = (bx - GROUPS * KW) * 64 + (tid >> 2);   // 0..8191
        int n  = o >> 8, oc = o & 255;
        const float* cr = c  + (size_t)n  * C_DIM + (tid & 3) * 32;
        const float* wr = cw + (size_t)oc * C_DIM + (tid & 3) * 32;
        float s = 0.f;
#pragma unroll 8
        for (int d = 0; d < 32; d++) s += cr[d] * wr[d];
        s += __shfl_down_sync(0xFFFFFFFFu, s, 2);
        s += __shfl_down_sync(0xFFFFFFFFu, s, 1);
        if ((tid & 3) == 0) g_ctx[o] = s;
    }
}

// ---------------------------------------------------------------------------
// conv_kernel: grouped conv as implicit GEMM (fp16 m16n8k16, fp32 accum).
// Block (lt, g, n): 256 l x 64 oc, 8 warps; warp = 32 l x 64 oc.
// Outer t = 4 ic-chunks of 16; taps inner. x (fp32) and B (fp16) streamed via
// one interleaved cp.async FIFO, 2 chunks ahead, 3-slot rings. 4 barriers.
// A operands packed fp32->fp16x2 in-loop (RN).
// ---------------------------------------------------------------------------
__global__ void __launch_bounds__(NTHR, 2)
conv_kernel(const float* __restrict__ x, const float* __restrict__ bias,
            float* __restrict__ out) {
    extern __shared__ char smem[];
    const uint32_t sb = smem_u32(smem);

    const int tid = threadIdx.x;
    const int wid = tid >> 5, lane = tid & 31;
    const int lt = blockIdx.x, g = blockIdx.y, n = blockIdx.z;
    const int l0 = lt * L_TILE;

    const float* xb = x + ((size_t)(n * C_IN + g * CPG)) * L_LEN + (l0 - PAD);
    const char*  bw = (const char*)(g_wt + (size_t)g * 18432);

    // --- issue helpers ---
    auto issue_x = [&](int t) {                    // x chunk t (16 ic rows) -> slot t%3
        uint32_t base = sb + SM_X + (t % 3) * X_SLOT_B;
        const float* src0 = xb + (size_t)(16 * t) * L_LEN;
#pragma unroll
        for (int it = 0; it < 5; it++) {           // 16 rows x 66 chunks = 1056
            int i = tid + it * NTHR;
            if (i < 1056) {
                int row = i / 66, c = i - row * 66;
                int gl = l0 - PAD + 4 * c;
                uint32_t sz = (gl >= 0 && gl <= L_LEN - 4) ? 16u : 0u;
                cp16z(base + (row * XS_STRIDE + 4 * c) * 4,
                      src0 + (size_t)row * L_LEN + 4 * c, sz);
            }
        }
    };
    auto issue_b = [&](int t) {                    // B chunk t -> slot t%3
        uint32_t base = sb + SM_B + (t % 3) * B_SLOT_B;
        const char* src = bw + (size_t)t * B_SLOT_B;
#pragma unroll
        for (int it = 0; it < 5; it++) {           // 18,432 B = 1152 chunks
            int i = tid + it * NTHR;
            if (i < 1152) cp16(base + i * 16, src + (size_t)i * 16);
        }
    };

    // ---- prologue: groups x0, B0, x1, B1 ----
    issue_x(0); CP_COMMIT();
    issue_b(0); CP_COMMIT();
    issue_x(1); CP_COMMIT();
    issue_b(1); CP_COMMIT();

    // ctx + bias for this (n, g) into smem
    if (tid < OPG) {
        int goc = g * OPG + tid;
        ((float*)(smem + SM_CTX))[tid] = g_ctx[n * C_OUT + goc] + bias[goc];
    }

    // ---- accumulators: warp tile 32 l x 64 oc = 2 (mi) x 8 (q) frags ----
    float d[2][8][4];
#pragma unroll
    for (int mi = 0; mi < 2; mi++)
#pragma unroll
        for (int f = 0; f < 8; f++)
#pragma unroll
            for (int r = 0; r < 4; r++) d[mi][f][r] = 0.f;

    const int ml  = wid * 32;
    const int gid = lane >> 2;     // fragment group id (l offset 0..7)
    const int tig = lane & 3;      // thread-in-group (ic pair selector)

#pragma unroll 1
    for (int t = 0; t < 4; t++) {
        // x(t), B(t) landed when <= 2 commit-pairs (t+1, t+2) pending
        CP_WAIT2();
        __syncthreads();           // cross-thread visibility + ring-slot safety

        if (t + 2 < 4) issue_x(t + 2);
        CP_COMMIT();
        if (t + 2 < 4) issue_b(t + 2);
        CP_COMMIT();

        const float* xsf  = (const float*)(smem + SM_X + (t % 3) * X_SLOT_B);
        const char*  bbsl = smem + SM_B + (t % 3) * B_SLOT_B;

#pragma unroll
        for (int k = 0; k < KW; k++) {
            // A fragments: 16 conflict-free LDS.32 + 8 RN packs
            uint32_t a[2][4];
            const float* xr = xsf + 2 * tig * XS_STRIDE + (ml + gid + k);
#pragma unroll
            for (int mi = 0; mi < 2; mi++) {
                const float* p  = xr + 16 * mi;
                const float* p8 = p + 8 * XS_STRIDE;
                a[mi][0] = packh2(p[XS_STRIDE],      p[0]);
                a[mi][1] = packh2(p[XS_STRIDE + 8],  p[8]);
                a[mi][2] = packh2(p8[XS_STRIDE],     p8[0]);
                a[mi][3] = packh2(p8[XS_STRIDE + 8], p8[8]);
            }
            // B fragments: 4 conflict-free LDS.128 (fp16x2 x4 per qq)
            uint4 bq[4];
            {
                const uint4* bsrc = (const uint4*)(bbsl + k * 2048) + lane;
#pragma unroll
                for (int qq = 0; qq < 4; qq++) bq[qq] = bsrc[qq * 32];
            }
#pragma unroll
            for (int mi = 0; mi < 2; mi++) {
#pragma unroll
                for (int qq = 0; qq < 4; qq++) {
                    mma_f16(d[mi][2 * qq],     a[mi], bq[qq].x, bq[qq].y);
                    mma_f16(d[mi][2 * qq + 1], a[mi], bq[qq].z, bq[qq].w);
                }
            }
        }
    }
    __syncthreads();   // all compute done before epilogue clobbers the rings

    // ---- epilogue: stage through smem (alias rings), coalesced float4 out ----
    float* ep = (float*)smem;             // [oc][l], stride EP_STRIDE
#pragma unroll
    for (int mi = 0; mi < 2; mi++) {
#pragma unroll
        for (int f = 0; f < 8; f++) {
            int l  = ml + 16 * mi + gid;
            int oc = 8 * f + 2 * tig;
            ep[oc * EP_STRIDE + l]           = d[mi][f][0];
            ep[(oc + 1) * EP_STRIDE + l]     = d[mi][f][1];
            ep[oc * EP_STRIDE + l + 8]       = d[mi][f][2];
            ep[(oc + 1) * EP_STRIDE + l + 8] = d[mi][f][3];
        }
    }
    __syncthreads();

    const float* sadd = (const float*)(smem + SM_CTX);
#pragma unroll
    for (int i = 0; i < 8; i++) {
        int oc  = wid * 8 + i;
        int goc = g * OPG + oc;
        float add = sadd[oc];
        const float4* src = (const float4*)(ep + oc * EP_STRIDE);
        float4* dst = (float4*)(out + ((size_t)(n * C_OUT + goc)) * L_LEN + l0);
#pragma unroll
        for (int it = 0; it < 2; it++) {
            float4 v = src[lane + it * 32];
            v.x += add; v.y += add; v.z += add; v.w += add;
            dst[lane + it * 32] = v;
        }
    }
}

// ---------------------------------------------------------------------------
extern "C" void kernel_launch(void* const* d_in, const int* in_sizes, int n_in,
                              void* d_out, int out_size) {
    const float* x    = (const float*)d_in[0];  // (32, 256, 4096)
    const float* c    = (const float*)d_in[1];  // (32, 128)
    const float* w    = (const float*)d_in[2];  // (256, 64, 9)
    const float* cw   = (const float*)d_in[3];  // (256, 128)
    const float* bias = (const float*)d_in[4];  // (256,)
    float* out = (float*)d_out;                 // (32, 256, 4096)

    cudaFuncSetAttribute(conv_kernel, cudaFuncAttributeMaxDynamicSharedMemorySize, SM_TOTAL);

    prep_kernel<<<GROUPS * KW + 128, 256>>>(w, c, cw);
    dim3 grid(L_LEN / L_TILE, GROUPS, N_B);     // (16, 4, 32)
    conv_kernel<<<grid, NTHR, SM_TOTAL>>>(x, bias, out);
}

// round 11
// speedup vs baseline: 2.5292x; 1.0420x over previous
#include <cuda_runtime.h>
#include <cstdint>

// ---------------- problem constants ----------------
#define N_B    32
#define C_IN   256
#define L_LEN  4096
#define C_OUT  256
#define KW     9
#define GROUPS 4
#define CPG    64
#define OPG    64
#define C_DIM  128
#define PAD    4

#define L_TILE 256
#define NTHR   256                          // 8 warps; warp tile = 32 l x 64 oc
#define XF_STRIDE 268                       // fp32 staging stride (words)
#define XH_STRIDE 264                       // fp16x2 rows; %32==8 -> conflict-free
#define EP_STRIDE 260                       // epilogue staging stride

// smem layout (bytes)
#define XF_SLOT_B (16 * XF_STRIDE * 4)      // 17,152 B per fp32 x chunk slot
#define B_SLOT_B  18432                     // 9 taps x 512 fp16x2 words per chunk
#define XH_B      (8 * XH_STRIDE * 4)       // 8,448 B packed A buffer
#define SM_XF     0                         // 2 x 17,152 = 34,304
#define SM_XH     (2 * XF_SLOT_B)           // 34,304 .. 42,752
#define SM_B      (SM_XH + XH_B)            // 3 x 18,432 = 55,296
#define SM_CTX    (SM_B + 3 * B_SLOT_B)     // 98,048
#define SM_TOTAL  (SM_CTX + 256)            // 98,304 B (x2 CTA/SM = 196,608)
// epilogue aliases [0, 66,560) -- dead after final barrier

// ---------------- device scratch ----------------
__device__ float g_ctx[N_B * C_OUT];
// B tiles: per g: [t=4][k=9] blocks of 512 fp16x2 words, m16n8k16 frag order
__device__ unsigned int g_wt[GROUPS * 4 * KW * 512];

__device__ __forceinline__ uint32_t smem_u32(const void* p) {
    uint32_t a;
    asm("{ .reg .u64 t; cvta.to.shared.u64 t, %1; cvt.u32.u64 %0, t; }" : "=r"(a) : "l"(p));
    return a;
}
__device__ __forceinline__ uint32_t packh2(float hi, float lo) {
    uint32_t r;
    asm("cvt.rn.f16x2.f32 %0, %1, %2;" : "=r"(r) : "f"(hi), "f"(lo));
    return r;
}
__device__ __forceinline__ void cp16(uint32_t dst, const void* src) {
    asm volatile("cp.async.cg.shared.global [%0], [%1], 16;" :: "r"(dst), "l"(src));
}
__device__ __forceinline__ void cp16z(uint32_t dst, const void* src, uint32_t src_size) {
    asm volatile("cp.async.cg.shared.global [%0], [%1], 16, %2;"
                 :: "r"(dst), "l"(src), "r"(src_size));
}
#define CP_COMMIT() asm volatile("cp.async.commit_group;" ::: "memory")
#define CP_WAIT2()  asm volatile("cp.async.wait_group 2;" ::: "memory")

__device__ __forceinline__ void mma_f16(float* d, const uint32_t* a, uint32_t b0, uint32_t b1) {
    asm("mma.sync.aligned.m16n8k16.row.col.f32.f16.f16.f32 "
        "{%0,%1,%2,%3}, {%4,%5,%6,%7}, {%8,%9}, {%0,%1,%2,%3};"
        : "+f"(d[0]), "+f"(d[1]), "+f"(d[2]), "+f"(d[3])
        : "r"(a[0]), "r"(a[1]), "r"(a[2]), "r"(a[3]), "r"(b0), "r"(b1));
}

// ---------------------------------------------------------------------------
// prep_kernel: blocks [0,36) -> fp16x2 B fragment tiles; [36,164) -> ctx GEMM.
// ---------------------------------------------------------------------------
__global__ void prep_kernel(const float* __restrict__ w,
                            const float* __restrict__ c,
                            const float* __restrict__ cw) {
    int bx = blockIdx.x, tid = threadIdx.x;
    if (bx < GROUPS * KW) {
        int g = bx / KW, k = bx - g * KW;
        for (int idx = tid; idx < 2048; idx += 256) {
            int r    = idx & 1;
            int qlo  = (idx >> 1) & 1;
            int lane = (idx >> 2) & 31;
            int qq   = (idx >> 7) & 3;
            int t    = idx >> 9;
            int oc   = 8 * (2 * qq + qlo) + (lane >> 2);
            int ic   = 16 * t + 2 * (lane & 3) + 8 * r;
            const float* wr = w + (size_t)(g * OPG + oc) * (CPG * KW) + k;
            float lo = wr[ic * KW];
            float hi = wr[(ic + 1) * KW];
            g_wt[(size_t)g * 18432 + (t * KW + k) * 512 +
                 (qq * 128 + lane * 4 + qlo * 2 + r)] = packh2(hi, lo);
        }
    } else {
        int o  = (bx - GROUPS * KW) * 64 + (tid >> 2);   // 0..8191
        int n  = o >> 8, oc = o & 255;
        const float* cr = c  + (size_t)n  * C_DIM + (tid & 3) * 32;
        const float* wr = cw + (size_t)oc * C_DIM + (tid & 3) * 32;
        float s = 0.f;
#pragma unroll 8
        for (int d = 0; d < 32; d++) s += cr[d] * wr[d];
        s += __shfl_down_sync(0xFFFFFFFFu, s, 2);
        s += __shfl_down_sync(0xFFFFFFFFu, s, 1);
        if ((tid & 3) == 0) g_ctx[o] = s;
    }
}

// ---------------------------------------------------------------------------
// conv_kernel: grouped conv as implicit GEMM (fp16 m16n8k16, fp32 accum).
// Block (lt, g, n): 256 l x 64 oc, 8 warps; warp = 32 l x 64 oc.
// Outer t = 4 ic-chunks of 16. x fp32 streamed (2-slot ring), converted to
// fp16x2 A-layout in smem (xh) per chunk; B fp16 streamed (3-slot ring).
// Mainloop: A = 8 conflict-free LDS.32 (pre-packed), B = 4 LDS.128, 16 MMAs.
// ---------------------------------------------------------------------------
__global__ void __launch_bounds__(NTHR, 2)
conv_kernel(const float* __restrict__ x, const float* __restrict__ bias,
            float* __restrict__ out) {
    extern __shared__ char smem[];
    const uint32_t sb = smem_u32(smem);

    const int tid = threadIdx.x;
    const int wid = tid >> 5, lane = tid & 31;
    const int lt = blockIdx.x, g = blockIdx.y, n = blockIdx.z;
    const int l0 = lt * L_TILE;

    const float* xb = x + ((size_t)(n * C_IN + g * CPG)) * L_LEN + (l0 - PAD);
    const char*  bw = (const char*)(g_wt + (size_t)g * 18432);

    // --- issue helpers ---
    auto issue_x = [&](int t) {                    // x chunk t (16 ic rows) -> slot t%2
        uint32_t base = sb + SM_XF + (t & 1) * XF_SLOT_B;
        const float* src0 = xb + (size_t)(16 * t) * L_LEN;
#pragma unroll
        for (int it = 0; it < 5; it++) {           // 16 rows x 66 quads = 1056
            int i = tid + it * NTHR;
            if (i < 1056) {
                int row = i / 66, c = i - row * 66;
                int gl = l0 - PAD + 4 * c;
                uint32_t sz = (gl >= 0 && gl <= L_LEN - 4) ? 16u : 0u;
                cp16z(base + (row * XF_STRIDE + 4 * c) * 4,
                      src0 + (size_t)row * L_LEN + 4 * c, sz);
            }
        }
    };
    auto issue_b = [&](int t) {                    // B chunk t -> slot t%3
        uint32_t base = sb + SM_B + (t % 3) * B_SLOT_B;
        const char* src = bw + (size_t)t * B_SLOT_B;
#pragma unroll
        for (int it = 0; it < 5; it++) {           // 18,432 B = 1152 chunks
            int i = tid + it * NTHR;
            if (i < 1152) cp16(base + i * 16, src + (size_t)i * 16);
        }
    };

    // ---- prologue: groups x0, B0, x1, B1 ----
    issue_x(0); CP_COMMIT();
    issue_b(0); CP_COMMIT();
    issue_x(1); CP_COMMIT();
    issue_b(1); CP_COMMIT();

    if (tid < OPG) {
        int goc = g * OPG + tid;
        ((float*)(smem + SM_CTX))[tid] = g_ctx[n * C_OUT + goc] + bias[goc];
    }

    // ---- accumulators ----
    float d[2][8][4];
#pragma unroll
    for (int mi = 0; mi < 2; mi++)
#pragma unroll
        for (int f = 0; f < 8; f++)
#pragma unroll
            for (int r = 0; r < 4; r++) d[mi][f][r] = 0.f;

    const int ml  = wid * 32;
    const int gid = lane >> 2;     // l offset within fragment (0..7)
    const int tig = lane & 3;      // ic-pair selector

#pragma unroll 1
    for (int t = 0; t < 4; t++) {
        // x(t), B(t) landed; previous compute done (ring-slot safety)
        CP_WAIT2();
        __syncthreads();

        // ---- convert fp32 chunk t -> packed fp16x2 A buffer xh[pair][l] ----
        {
            const float* xsf = (const float*)(smem + SM_XF + (t & 1) * XF_SLOT_B);
            uint32_t* xh = (uint32_t*)(smem + SM_XH);
#pragma unroll
            for (int it = 0; it < 3; it++) {       // 8 pairs x 66 quads = 528
                int i = tid + it * NTHR;
                if (i < 528) {
                    int p = i / 66, c = (i - p * 66) * 4;
                    float4 v0 = *(const float4*)(xsf + (2 * p)     * XF_STRIDE + c);
                    float4 v1 = *(const float4*)(xsf + (2 * p + 1) * XF_STRIDE + c);
                    uint4 o;
                    o.x = packh2(v1.x, v0.x);
                    o.y = packh2(v1.y, v0.y);
                    o.z = packh2(v1.z, v0.z);
                    o.w = packh2(v1.w, v0.w);
                    *(uint4*)(xh + p * XH_STRIDE + c) = o;
                }
            }
        }
        __syncthreads();           // xh ready; fp32 slot t now free

        // issue t+2 (fp32 slot t reused; B slot (t+2)%3 untouched by t, t+1)
        if (t + 2 < 4) issue_x(t + 2);
        CP_COMMIT();
        if (t + 2 < 4) issue_b(t + 2);
        CP_COMMIT();

        const uint32_t* xh  = (const uint32_t*)(smem + SM_XH);
        const char*    bbsl = smem + SM_B + (t % 3) * B_SLOT_B;
        const uint32_t* xr0 = xh + tig * XH_STRIDE + (ml + gid);
        const uint32_t* xr4 = xr0 + 4 * XH_STRIDE;

#pragma unroll
        for (int k = 0; k < KW; k++) {
            // A fragments: 8 conflict-free LDS.32 (pre-packed fp16x2)
            uint32_t a[2][4];
#pragma unroll
            for (int mi = 0; mi < 2; mi++) {
                a[mi][0] = xr0[k + 16 * mi];
                a[mi][1] = xr0[k + 16 * mi + 8];
                a[mi][2] = xr4[k + 16 * mi];
                a[mi][3] = xr4[k + 16 * mi + 8];
            }
            // B fragments: 4 conflict-free LDS.128
            uint4 bq[4];
            {
                const uint4* bsrc = (const uint4*)(bbsl + k * 2048) + lane;
#pragma unroll
                for (int qq = 0; qq < 4; qq++) bq[qq] = bsrc[qq * 32];
            }
#pragma unroll
            for (int mi = 0; mi < 2; mi++) {
#pragma unroll
                for (int qq = 0; qq < 4; qq++) {
                    mma_f16(d[mi][2 * qq],     a[mi], bq[qq].x, bq[qq].y);
                    mma_f16(d[mi][2 * qq + 1], a[mi], bq[qq].z, bq[qq].w);
                }
            }
        }
    }
    __syncthreads();   // all compute done before epilogue clobbers buffers

    // ---- epilogue: stage through smem, coalesced float4 out ----
    float* ep = (float*)smem;             // [oc][l], stride EP_STRIDE
#pragma unroll
    for (int mi = 0; mi < 2; mi++) {
#pragma unroll
        for (int f = 0; f < 8; f++) {
            int l  = ml + 16 * mi + gid;
            int oc = 8 * f + 2 * tig;
            ep[oc * EP_STRIDE + l]           = d[mi][f][0];
            ep[(oc + 1) * EP_STRIDE + l]     = d[mi][f][1];
            ep[oc * EP_STRIDE + l + 8]       = d[mi][f][2];
            ep[(oc + 1) * EP_STRIDE + l + 8] = d[mi][f][3];
        }
    }
    __syncthreads();

    const float* sadd = (const float*)(smem + SM_CTX);
#pragma unroll
    for (int i = 0; i < 8; i++) {
        int oc  = wid * 8 + i;
        int goc = g * OPG + oc;
        float add = sadd[oc];
        const float4* src = (const float4*)(ep + oc * EP_STRIDE);
        float4* dst = (float4*)(out + ((size_t)(n * C_OUT + goc)) * L_LEN + l0);
#pragma unroll
        for (int it = 0; it < 2; it++) {
            float4 v = src[lane + it * 32];
            v.x += add; v.y += add; v.z += add; v.w += add;
            dst[lane + it * 32] = v;
        }
    }
}

// ---------------------------------------------------------------------------
extern "C" void kernel_launch(void* const* d_in, const int* in_sizes, int n_in,
                              void* d_out, int out_size) {
    const float* x    = (const float*)d_in[0];  // (32, 256, 4096)
    const float* c    = (const float*)d_in[1];  // (32, 128)
    const float* w    = (const float*)d_in[2];  // (256, 64, 9)
    const float* cw   = (const float*)d_in[3];  // (256, 128)
    const float* bias = (const float*)d_in[4];  // (256,)
    float* out = (float*)d_out;                 // (32, 256, 4096)

    cudaFuncSetAttribute(conv_kernel, cudaFuncAttributeMaxDynamicSharedMemorySize, SM_TOTAL);

    prep_kernel<<<GROUPS * KW + 128, 256>>>(w, c, cw);
    dim3 grid(L_LEN / L_TILE, GROUPS, N_B);     // (16, 4, 32)
    conv_kernel<<<grid, NTHR, SM_TOTAL>>>(x, bias, out);
}